// round 10
// baseline (speedup 1.0000x reference)
#include <cuda_runtime.h>
#include <cuda_bf16.h>

// out[i] = sin(in[i,0]) * sin(in[i,1]); N = 16777216 rows.
// Minimum-queue-contention shape: 4 outputs/thread, exactly ONE LDG.256
// (32B) + ONE STG.128 per thread => MLP_p1 = 1, minimal cross-CTA L1tex
// queue spread (B300 spr_max floor ~1.10 vs ~1.31 at MLP_p1=4).
// Grid 16384 x 256, max occupancy. One warp-load = 8 lines in flight;
// ~64 warps/SM keeps >500 lines outstanding -> DRAM latency fully hidden.

__device__ __forceinline__ void ld256(const float4* p, float4& q0, float4& q1) {
    unsigned long long a, b, c, d;
    asm("ld.global.nc.v4.b64 {%0,%1,%2,%3}, [%4];"
        : "=l"(a), "=l"(b), "=l"(c), "=l"(d) : "l"(p));
    q0.x = __uint_as_float((unsigned)a); q0.y = __uint_as_float((unsigned)(a >> 32));
    q0.z = __uint_as_float((unsigned)b); q0.w = __uint_as_float((unsigned)(b >> 32));
    q1.x = __uint_as_float((unsigned)c); q1.y = __uint_as_float((unsigned)(c >> 32));
    q1.z = __uint_as_float((unsigned)d); q1.w = __uint_as_float((unsigned)(d >> 32));
}

__global__ __launch_bounds__(256) void sin_prod_kernel(
    const float4* __restrict__ in,   // pairs: .x=a,.y=b,.z=a',.w=b'
    float4* __restrict__ out,
    int n4)                          // number of 4-row groups = N/4
{
    int i = blockIdx.x * blockDim.x + threadIdx.x;
    if (i >= n4) return;

    float4 p0, p1;
    ld256(in + 2 * (size_t)i, p0, p1);   // 32B: rows 4i..4i+3

    float4 r;
    r.x = __sinf(p0.x) * __sinf(p0.y);
    r.y = __sinf(p0.z) * __sinf(p0.w);
    r.z = __sinf(p1.x) * __sinf(p1.y);
    r.w = __sinf(p1.z) * __sinf(p1.w);

    out[i] = r;
}

extern "C" void kernel_launch(void* const* d_in, const int* in_sizes, int n_in,
                              void* d_out, int out_size)
{
    const float* in = (const float*)d_in[0];
    float* out = (float*)d_out;

    int n = out_size;          // rows (16777216), divisible by 4
    int n4 = n / 4;            // 4194304 groups

    int threads = 256;
    int blocks = (n4 + threads - 1) / threads;   // 16384
    sin_prod_kernel<<<blocks, threads>>>(
        (const float4*)in, (float4*)out, n4);
}

// round 11
// speedup vs baseline: 1.0067x; 1.0067x over previous
#include <cuda_runtime.h>
#include <cuda_bf16.h>

// out[i] = sin(in[i,0]) * sin(in[i,1]); N = 16777216 rows.
// Persistent grid-stride kernel: exactly 1 wave (148 SMs x 8 CTAs x 256 thr),
// each thread loops ~14 iterations of {1x LDG.256, 1x STG.128}. Eliminates
// the ~13 wave transitions + per-wave straggler tails of the one-shot grids
// (all of which plateaued at 27.7-28.6us / ~75% DRAM).

__device__ __forceinline__ void ld256(const float4* p, float4& q0, float4& q1) {
    unsigned long long a, b, c, d;
    asm("ld.global.nc.v4.b64 {%0,%1,%2,%3}, [%4];"
        : "=l"(a), "=l"(b), "=l"(c), "=l"(d) : "l"(p));
    q0.x = __uint_as_float((unsigned)a); q0.y = __uint_as_float((unsigned)(a >> 32));
    q0.z = __uint_as_float((unsigned)b); q0.w = __uint_as_float((unsigned)(b >> 32));
    q1.x = __uint_as_float((unsigned)c); q1.y = __uint_as_float((unsigned)(c >> 32));
    q1.z = __uint_as_float((unsigned)d); q1.w = __uint_as_float((unsigned)(d >> 32));
}

__global__ __launch_bounds__(256) void sin_prod_kernel(
    const float4* __restrict__ in,   // pairs: .x=a,.y=b,.z=a',.w=b'
    float4* __restrict__ out,
    int n4)                          // number of 4-row groups = N/4
{
    int stride = gridDim.x * blockDim.x;           // total threads
    for (int i = blockIdx.x * blockDim.x + threadIdx.x; i < n4; i += stride) {
        float4 p0, p1;
        ld256(in + 2 * (size_t)i, p0, p1);         // 32B: rows 4i..4i+3

        float4 r;
        r.x = __sinf(p0.x) * __sinf(p0.y);
        r.y = __sinf(p0.z) * __sinf(p0.w);
        r.z = __sinf(p1.x) * __sinf(p1.y);
        r.w = __sinf(p1.z) * __sinf(p1.w);

        out[i] = r;
    }
}

extern "C" void kernel_launch(void* const* d_in, const int* in_sizes, int n_in,
                              void* d_out, int out_size)
{
    const float* in = (const float*)d_in[0];
    float* out = (float*)d_out;

    int n = out_size;          // rows (16777216), divisible by 4
    int n4 = n / 4;            // 4194304 groups

    // persistent single-wave grid: 148 SMs x 8 CTAs (regs=18 -> warp-limited 8/SM)
    int threads = 256;
    int blocks = 148 * 8;      // 1184
    sin_prod_kernel<<<blocks, threads>>>(
        (const float4*)in, (float4*)out, n4);
}

// round 12
// speedup vs baseline: 1.0077x; 1.0010x over previous
#include <cuda_runtime.h>
#include <cuda_bf16.h>

// out[i] = sin(in[i,0]) * sin(in[i,1]); N = 16777216 rows.
// Persistent single-wave grid (148 SMs x 8 CTAs x 256 thr), each iteration:
//   2x LDG.256 (back-to-back, MLP=2) -> 8 sin-pairs -> 1x STG.256.
// 256-bit store halves store-path issue slots/wavefronts vs 2x STG.128.

__device__ __forceinline__ void ld256(const float4* p, float4& q0, float4& q1) {
    unsigned long long a, b, c, d;
    asm("ld.global.nc.v4.b64 {%0,%1,%2,%3}, [%4];"
        : "=l"(a), "=l"(b), "=l"(c), "=l"(d) : "l"(p));
    q0.x = __uint_as_float((unsigned)a); q0.y = __uint_as_float((unsigned)(a >> 32));
    q0.z = __uint_as_float((unsigned)b); q0.w = __uint_as_float((unsigned)(b >> 32));
    q1.x = __uint_as_float((unsigned)c); q1.y = __uint_as_float((unsigned)(c >> 32));
    q1.z = __uint_as_float((unsigned)d); q1.w = __uint_as_float((unsigned)(d >> 32));
}

__device__ __forceinline__ unsigned long long pack2(float lo, float hi) {
    return (unsigned long long)__float_as_uint(lo)
         | ((unsigned long long)__float_as_uint(hi) << 32);
}

__device__ __forceinline__ void st256(float4* p,
                                      const float4& r0, const float4& r1) {
    unsigned long long a = pack2(r0.x, r0.y);
    unsigned long long b = pack2(r0.z, r0.w);
    unsigned long long c = pack2(r1.x, r1.y);
    unsigned long long d = pack2(r1.z, r1.w);
    asm volatile("st.global.v4.b64 [%0], {%1,%2,%3,%4};"
                 :: "l"(p), "l"(a), "l"(b), "l"(c), "l"(d) : "memory");
}

__global__ __launch_bounds__(256) void sin_prod_kernel(
    const float4* __restrict__ in,   // pairs: .x=a,.y=b,.z=a',.w=b'
    float4* __restrict__ out,
    int n8)                          // number of 8-row groups = N/8
{
    int stride = gridDim.x * blockDim.x;
    for (int i = blockIdx.x * blockDim.x + threadIdx.x; i < n8; i += stride) {
        const float4* pin = in + 4 * (size_t)i;   // 64B per group

        float4 p0, p1, p2, p3;
        ld256(pin + 0, p0, p1);   // back-to-back: 2 outstanding LDG.256
        ld256(pin + 2, p2, p3);

        float4 r0, r1;
        r0.x = __sinf(p0.x) * __sinf(p0.y);
        r0.y = __sinf(p0.z) * __sinf(p0.w);
        r0.z = __sinf(p1.x) * __sinf(p1.y);
        r0.w = __sinf(p1.z) * __sinf(p1.w);
        r1.x = __sinf(p2.x) * __sinf(p2.y);
        r1.y = __sinf(p2.z) * __sinf(p2.w);
        r1.z = __sinf(p3.x) * __sinf(p3.y);
        r1.w = __sinf(p3.z) * __sinf(p3.w);

        st256(out + 2 * (size_t)i, r0, r1);
    }
}

extern "C" void kernel_launch(void* const* d_in, const int* in_sizes, int n_in,
                              void* d_out, int out_size)
{
    const float* in = (const float*)d_in[0];
    float* out = (float*)d_out;

    int n = out_size;          // rows (16777216), divisible by 8
    int n8 = n / 8;            // 2097152 groups

    // persistent single-wave grid: 148 SMs x 8 CTAs x 256 threads
    int threads = 256;
    int blocks = 148 * 8;      // 1184
    sin_prod_kernel<<<blocks, threads>>>(
        (const float4*)in, (float4*)out, n8);
}